// round 2
// baseline (speedup 1.0000x reference)
#include <cuda_runtime.h>
#include <cuda_bf16.h>
#include <cstdint>

#define S_LEN  512
#define BATCH  64
#define HID    1024
#define LAYERS 3
#define G3     (3*HID)        // 3072 gate rows per layer
#define BH     (BATCH*HID)    // 65536

// ---------------- scratch (device globals; no runtime allocation) ----------
__device__ __nv_bfloat16 g_xhi[(size_t)S_LEN*BH];     // bf16 splits of external x
__device__ __nv_bfloat16 g_xlo[(size_t)S_LEN*BH];
__device__ __nv_bfloat16 g_wih_hi[(size_t)LAYERS*G3*HID];
__device__ __nv_bfloat16 g_wih_lo[(size_t)LAYERS*G3*HID];
__device__ __nv_bfloat16 g_whh_hi[(size_t)LAYERS*G3*HID];
__device__ __nv_bfloat16 g_whh_lo[(size_t)LAYERS*G3*HID];
__device__ float         g_h  [LAYERS*2*BH];          // fp32 h state, parity double buffer
__device__ __nv_bfloat16 g_hhi[LAYERS*2*BH];          // bf16 splits of h state
__device__ __nv_bfloat16 g_hlo[LAYERS*2*BH];

// ---------------- helpers ---------------------------------------------------
__device__ __forceinline__ void ldsm4(uint32_t r[4], const __nv_bfloat16* p) {
    uint32_t a = (uint32_t)__cvta_generic_to_shared(p);
    asm volatile("ldmatrix.sync.aligned.m8n8.x4.shared.b16 {%0,%1,%2,%3}, [%4];"
                 : "=r"(r[0]), "=r"(r[1]), "=r"(r[2]), "=r"(r[3]) : "r"(a));
}

__device__ __forceinline__ void mma16816(float c[4], const uint32_t a[4],
                                         uint32_t b0, uint32_t b1) {
    asm volatile("mma.sync.aligned.m16n8k16.row.col.f32.bf16.bf16.f32 "
                 "{%0,%1,%2,%3}, {%4,%5,%6,%7}, {%8,%9}, {%0,%1,%2,%3};"
                 : "+f"(c[0]), "+f"(c[1]), "+f"(c[2]), "+f"(c[3])
                 : "r"(a[0]), "r"(a[1]), "r"(a[2]), "r"(a[3]), "r"(b0), "r"(b1));
}

__device__ __forceinline__ void split2(float v, __nv_bfloat16& hi, __nv_bfloat16& lo) {
    hi = __float2bfloat16_rn(v);
    lo = __float2bfloat16_rn(v - __bfloat162float(hi));
}

// ---------------- prep kernels ---------------------------------------------
__global__ void split_weights_kernel(const float* __restrict__ wih,
                                     const float* __restrict__ whh) {
    size_t i = (size_t)blockIdx.x * blockDim.x + threadIdx.x;
    if (i >= (size_t)LAYERS * G3 * HID) return;
    __nv_bfloat16 hi, lo;
    split2(wih[i], hi, lo); g_wih_hi[i] = hi; g_wih_lo[i] = lo;
    split2(whh[i], hi, lo); g_whh_hi[i] = hi; g_whh_lo[i] = lo;
}

__global__ void split_x_kernel(const float* __restrict__ x) {
    size_t i = (size_t)blockIdx.x * blockDim.x + threadIdx.x;
    if (i >= (size_t)S_LEN * BH) return;
    __nv_bfloat16 hi, lo;
    split2(x[i], hi, lo); g_xhi[i] = hi; g_xlo[i] = lo;
}

__global__ void init_h_kernel(const float* __restrict__ h0) {
    size_t i = (size_t)blockIdx.x * blockDim.x + threadIdx.x;
    if (i >= (size_t)LAYERS * BH) return;
    int l = (int)(i / BH);
    size_t j = i % BH;
    float v = h0[i];
    size_t dst = ((size_t)l * 2 + 0) * BH + j;   // parity 0 = state for t=0
    g_h[dst] = v;
    __nv_bfloat16 hi, lo;
    split2(v, hi, lo); g_hhi[dst] = hi; g_hlo[dst] = lo;
}

// ---------------- fused GRU step (layer-pipelined) --------------------------
// grid (32, LAYERS), 256 threads. CTA: 64 batch x 32 hidden units (96 gate rows).
// Per step computes gi = x_t @ Wih^T and gh = h @ Whh^T separately (needed for
// the n-gate), each as bf16x3 split GEMM, then the pointwise GRU update.
__global__ __launch_bounds__(256) void gru_step_kernel(
    int gs, const float* __restrict__ bih, const float* __restrict__ bhh,
    float* __restrict__ out)
{
    const int l = blockIdx.y;
    const int t = gs - l;
    if (t < 0 || t >= S_LEN) return;

    const int u0   = blockIdx.x * 32;
    const int tid  = threadIdx.x;
    const int lane = tid & 31;
    const int wid  = tid >> 5;
    const int wm   = wid >> 1;   // 0..3  -> batch rows 16*wm
    const int wn   = wid & 1;    // 0..1  -> gate cols 48*wn

    __shared__ __align__(16) unsigned char smem_raw[49152];
    __nv_bfloat16* sAhi = (__nv_bfloat16*)smem_raw;   // 64 x 72
    __nv_bfloat16* sAlo = sAhi + 64 * 72;
    __nv_bfloat16* sWhi = sAlo + 64 * 72;             // 96 x 72
    __nv_bfloat16* sWlo = sWhi + 96 * 72;

    const int par = t & 1;

    const __nv_bfloat16* gA_hi[2];
    const __nv_bfloat16* gA_lo[2];
    const __nv_bfloat16* gW_hi[2];
    const __nv_bfloat16* gW_lo[2];
    if (l == 0) {
        gA_hi[0] = g_xhi + (size_t)t * BH;
        gA_lo[0] = g_xlo + (size_t)t * BH;
    } else {
        size_t o = ((size_t)(l - 1) * 2 + (par ^ 1)) * BH;  // h_{l-1}[t]
        gA_hi[0] = g_hhi + o;  gA_lo[0] = g_hlo + o;
    }
    {
        size_t o = ((size_t)l * 2 + par) * BH;               // h_l[t-1]
        gA_hi[1] = g_hhi + o;  gA_lo[1] = g_hlo + o;
    }
    {
        size_t o = (size_t)l * G3 * HID;
        gW_hi[0] = g_wih_hi + o;  gW_lo[0] = g_wih_lo + o;
        gW_hi[1] = g_whh_hi + o;  gW_lo[1] = g_whh_lo + o;
    }

    float acc[2][6][4];
#pragma unroll
    for (int p = 0; p < 2; ++p)
#pragma unroll
        for (int j = 0; j < 6; ++j)
#pragma unroll
            for (int q = 0; q < 4; ++q) acc[p][j][q] = 0.f;

    // ldmatrix lane address components
    const int rowA  = wm * 16 + (lane & 15);
    const int ahalf = (lane >> 4) * 8;
    const int rowB  = (lane & 7) + ((lane & 16) ? 8 : 0);
    const int bhalf = (lane & 8) ? 8 : 0;

#pragma unroll
    for (int ph = 0; ph < 2; ++ph) {                 // 0: x-path (gi), 1: h-path (gh)
        const __nv_bfloat16* Ahi = gA_hi[ph];
        const __nv_bfloat16* Alo = gA_lo[ph];
        const __nv_bfloat16* Whi = gW_hi[ph];
        const __nv_bfloat16* Wlo = gW_lo[ph];
        for (int kc = 0; kc < 16; ++kc) {            // K=1024 in chunks of 64
            const int kb = kc * 64;
            __syncthreads();
#pragma unroll
            for (int i = tid; i < 512; i += 256) {   // A tile: 64 rows x 64 halfs
                int row = i >> 3, v = (i & 7) * 8;
                *(uint4*)(sAhi + row * 72 + v) =
                    *(const uint4*)(Ahi + (size_t)row * HID + kb + v);
                *(uint4*)(sAlo + row * 72 + v) =
                    *(const uint4*)(Alo + (size_t)row * HID + kb + v);
            }
#pragma unroll
            for (int i = tid; i < 768; i += 256) {   // W tile: 96 gate rows x 64 halfs
                int rr = i >> 3, v = (i & 7) * 8;
                size_t grow = (size_t)(rr >> 5) * HID + u0 + (rr & 31); // r/z/n groups
                *(uint4*)(sWhi + rr * 72 + v) =
                    *(const uint4*)(Whi + grow * HID + kb + v);
                *(uint4*)(sWlo + rr * 72 + v) =
                    *(const uint4*)(Wlo + grow * HID + kb + v);
            }
            __syncthreads();
#pragma unroll
            for (int ks = 0; ks < 4; ++ks) {
                uint32_t ah[4], al[4];
                ldsm4(ah, sAhi + rowA * 72 + ks * 16 + ahalf);
                ldsm4(al, sAlo + rowA * 72 + ks * 16 + ahalf);
#pragma unroll
                for (int j = 0; j < 3; ++j) {
                    uint32_t bh[4], bl[4];
                    int boff = (wn * 48 + j * 16 + rowB) * 72 + ks * 16 + bhalf;
                    ldsm4(bh, sWhi + boff);
                    ldsm4(bl, sWlo + boff);
                    // bf16x3: hi*hi + lo*hi + hi*lo
                    mma16816(acc[ph][2 * j],     ah, bh[0], bh[1]);
                    mma16816(acc[ph][2 * j],     al, bh[0], bh[1]);
                    mma16816(acc[ph][2 * j],     ah, bl[0], bl[1]);
                    mma16816(acc[ph][2 * j + 1], ah, bh[2], bh[3]);
                    mma16816(acc[ph][2 * j + 1], al, bh[2], bh[3]);
                    mma16816(acc[ph][2 * j + 1], ah, bl[2], bl[3]);
                }
            }
        }
    }

    // ---- epilogue: accums -> smem, then pointwise GRU update ----
    __syncthreads();
    float* sGI = (float*)smem_raw;       // 64 x 96
    float* sGH = sGI + 64 * 96;          // 64 x 96

    {
        int g  = lane >> 2;
        int t4 = lane & 3;
#pragma unroll
        for (int j = 0; j < 6; ++j) {
            int col = wn * 48 + j * 8 + t4 * 2;
            int r0  = wm * 16 + g;
            sGI[r0 * 96 + col]           = acc[0][j][0];
            sGI[r0 * 96 + col + 1]       = acc[0][j][1];
            sGI[(r0 + 8) * 96 + col]     = acc[0][j][2];
            sGI[(r0 + 8) * 96 + col + 1] = acc[0][j][3];
            sGH[r0 * 96 + col]           = acc[1][j][0];
            sGH[r0 * 96 + col + 1]       = acc[1][j][1];
            sGH[(r0 + 8) * 96 + col]     = acc[1][j][2];
            sGH[(r0 + 8) * 96 + col + 1] = acc[1][j][3];
        }
    }
    __syncthreads();

    const int lG = l * G3;
    const float* bihp = bih + lG;
    const float* bhhp = bhh + lG;
    const float* hsrc = g_h + ((size_t)l * 2 + par) * BH;
    float*       hdst = g_h + ((size_t)l * 2 + (par ^ 1)) * BH;
    __nv_bfloat16* hhid = g_hhi + ((size_t)l * 2 + (par ^ 1)) * BH;
    __nv_bfloat16* hlod = g_hlo + ((size_t)l * 2 + (par ^ 1)) * BH;

#pragma unroll
    for (int it = 0; it < 8; ++it) {
        int idx = it * 256 + tid;
        int b = idx >> 5, u = idx & 31;
        int ug = u0 + u;
        float gi_r = sGI[b * 96 + u],       gh_r = sGH[b * 96 + u];
        float gi_z = sGI[b * 96 + 32 + u],  gh_z = sGH[b * 96 + 32 + u];
        float gi_n = sGI[b * 96 + 64 + u],  gh_n = sGH[b * 96 + 64 + u];
        float pr = gi_r + bihp[ug]           + gh_r + bhhp[ug];
        float pz = gi_z + bihp[HID + ug]     + gh_z + bhhp[HID + ug];
        float rg = 1.f / (1.f + __expf(-pr));
        float zg = 1.f / (1.f + __expf(-pz));
        float nn = tanhf(gi_n + bihp[2 * HID + ug] + rg * (gh_n + bhhp[2 * HID + ug]));
        float hold = hsrc[(size_t)b * HID + ug];
        float hn = (1.f - zg) * nn + zg * hold;
        hdst[(size_t)b * HID + ug] = hn;
        __nv_bfloat16 hi, lo;
        split2(hn, hi, lo);
        hhid[(size_t)b * HID + ug] = hi;
        hlod[(size_t)b * HID + ug] = lo;
        if (l == LAYERS - 1)
            out[(size_t)t * BH + (size_t)b * HID + ug] = hn;
    }
}

// ---------------- launch -----------------------------------------------------
extern "C" void kernel_launch(void* const* d_in, const int* in_sizes, int n_in,
                              void* d_out, int out_size)
{
    const float* x   = (const float*)d_in[0];
    const float* h0  = (const float*)d_in[1];
    const float* wih = (const float*)d_in[2];
    const float* whh = (const float*)d_in[3];
    const float* bih = (const float*)d_in[4];
    const float* bhh = (const float*)d_in[5];
    float* out = (float*)d_out;

    {
        size_t n = (size_t)LAYERS * G3 * HID;
        split_weights_kernel<<<(unsigned)((n + 255) / 256), 256>>>(wih, whh);
    }
    {
        size_t n = (size_t)S_LEN * BH;
        split_x_kernel<<<(unsigned)((n + 255) / 256), 256>>>(x);
    }
    {
        size_t n = (size_t)LAYERS * BH;
        init_h_kernel<<<(unsigned)((n + 255) / 256), 256>>>(h0);
    }
    for (int gs = 0; gs < S_LEN + LAYERS - 1; ++gs)
        gru_step_kernel<<<dim3(32, LAYERS), 256>>>(gs, bih, bhh, out);
}

// round 3
// speedup vs baseline: 1.2592x; 1.2592x over previous
#include <cuda_runtime.h>
#include <cuda_bf16.h>
#include <cstdint>

#define S_LEN  512
#define BATCH  64
#define HID    1024
#define LAYERS 3
#define G3     (3*HID)        // 3072 gate rows per layer
#define BH     (BATCH*HID)    // 65536

#define NCHUNK 32             // 16 chunks of K=64 per path, 2 paths
#define DEPTH  4              // cp.async ring depth
#define BUF_HALFS (2*64*72 + 2*96*72)   // 23040 halfs = 46080 B per buffer
#define SMEM_BYTES (DEPTH * BUF_HALFS * 2)  // 184320 B

// ---------------- scratch (device globals; no runtime allocation) ----------
__device__ __nv_bfloat16 g_xhi[(size_t)S_LEN*BH];
__device__ __nv_bfloat16 g_xlo[(size_t)S_LEN*BH];
__device__ __nv_bfloat16 g_wih_hi[(size_t)LAYERS*G3*HID];
__device__ __nv_bfloat16 g_wih_lo[(size_t)LAYERS*G3*HID];
__device__ __nv_bfloat16 g_whh_hi[(size_t)LAYERS*G3*HID];
__device__ __nv_bfloat16 g_whh_lo[(size_t)LAYERS*G3*HID];
__device__ float         g_h  [LAYERS*2*BH];          // fp32 h, parity double buffer
__device__ __nv_bfloat16 g_hhi[LAYERS*2*BH];
__device__ __nv_bfloat16 g_hlo[LAYERS*2*BH];

// ---------------- helpers ---------------------------------------------------
__device__ __forceinline__ void ldsm4(uint32_t r[4], const __nv_bfloat16* p) {
    uint32_t a = (uint32_t)__cvta_generic_to_shared(p);
    asm volatile("ldmatrix.sync.aligned.m8n8.x4.shared.b16 {%0,%1,%2,%3}, [%4];"
                 : "=r"(r[0]), "=r"(r[1]), "=r"(r[2]), "=r"(r[3]) : "r"(a));
}

__device__ __forceinline__ void mma16816(float c[4], const uint32_t a[4],
                                         uint32_t b0, uint32_t b1) {
    asm volatile("mma.sync.aligned.m16n8k16.row.col.f32.bf16.bf16.f32 "
                 "{%0,%1,%2,%3}, {%4,%5,%6,%7}, {%8,%9}, {%0,%1,%2,%3};"
                 : "+f"(c[0]), "+f"(c[1]), "+f"(c[2]), "+f"(c[3])
                 : "r"(a[0]), "r"(a[1]), "r"(a[2]), "r"(a[3]), "r"(b0), "r"(b1));
}

__device__ __forceinline__ void split2(float v, __nv_bfloat16& hi, __nv_bfloat16& lo) {
    hi = __float2bfloat16_rn(v);
    lo = __float2bfloat16_rn(v - __bfloat162float(hi));
}

__device__ __forceinline__ void cp16(__nv_bfloat16* dst, const __nv_bfloat16* src) {
    uint32_t d = (uint32_t)__cvta_generic_to_shared(dst);
    asm volatile("cp.async.cg.shared.global [%0], [%1], 16;" :: "r"(d), "l"(src));
}

// ---------------- prep kernels ---------------------------------------------
__global__ void split_weights_kernel(const float* __restrict__ wih,
                                     const float* __restrict__ whh) {
    size_t i = (size_t)blockIdx.x * blockDim.x + threadIdx.x;
    if (i >= (size_t)LAYERS * G3 * HID) return;
    __nv_bfloat16 hi, lo;
    split2(wih[i], hi, lo); g_wih_hi[i] = hi; g_wih_lo[i] = lo;
    split2(whh[i], hi, lo); g_whh_hi[i] = hi; g_whh_lo[i] = lo;
}

__global__ void split_x_kernel(const float* __restrict__ x) {
    size_t i = (size_t)blockIdx.x * blockDim.x + threadIdx.x;
    if (i >= (size_t)S_LEN * BH) return;
    __nv_bfloat16 hi, lo;
    split2(x[i], hi, lo); g_xhi[i] = hi; g_xlo[i] = lo;
}

__global__ void init_h_kernel(const float* __restrict__ h0) {
    size_t i = (size_t)blockIdx.x * blockDim.x + threadIdx.x;
    if (i >= (size_t)LAYERS * BH) return;
    int l = (int)(i / BH);
    size_t j = i % BH;
    float v = h0[i];
    size_t dst = ((size_t)l * 2 + 0) * BH + j;
    g_h[dst] = v;
    __nv_bfloat16 hi, lo;
    split2(v, hi, lo); g_hhi[dst] = hi; g_hlo[dst] = lo;
}

// ---------------- chunk load/compute ----------------------------------------
__device__ __forceinline__ void load_chunk(
    __nv_bfloat16* buf,
    const __nv_bfloat16* __restrict__ Ahi, const __nv_bfloat16* __restrict__ Alo,
    const __nv_bfloat16* __restrict__ Whi, const __nv_bfloat16* __restrict__ Wlo,
    int kb, int u0, int tid)
{
    __nv_bfloat16* sAhi = buf;
    __nv_bfloat16* sAlo = buf + 64 * 72;
    __nv_bfloat16* sWhi = buf + 2 * 64 * 72;
    __nv_bfloat16* sWlo = sWhi + 96 * 72;
#pragma unroll
    for (int i = tid; i < 512; i += 256) {           // A tiles: 64 rows x 64 halfs
        int row = i >> 3, v = (i & 7) * 8;
        cp16(sAhi + row * 72 + v, Ahi + (size_t)row * HID + kb + v);
        cp16(sAlo + row * 72 + v, Alo + (size_t)row * HID + kb + v);
    }
#pragma unroll
    for (int i = tid; i < 768; i += 256) {           // W tiles: 96 gate rows x 64 halfs
        int rr = i >> 3, v = (i & 7) * 8;
        size_t grow = (size_t)(rr >> 5) * HID + u0 + (rr & 31);
        cp16(sWhi + rr * 72 + v, Whi + grow * HID + kb + v);
        cp16(sWlo + rr * 72 + v, Wlo + grow * HID + kb + v);
    }
}

__device__ __forceinline__ void compute_chunk(
    const __nv_bfloat16* buf, float (*acc)[4],
    int rowA, int ahalf, int rowB, int bhalf, int wn)
{
    const __nv_bfloat16* sAhi = buf;
    const __nv_bfloat16* sAlo = buf + 64 * 72;
    const __nv_bfloat16* sWhi = buf + 2 * 64 * 72;
    const __nv_bfloat16* sWlo = sWhi + 96 * 72;
#pragma unroll
    for (int ks = 0; ks < 4; ++ks) {
        uint32_t ah[4], al[4];
        ldsm4(ah, sAhi + rowA * 72 + ks * 16 + ahalf);
        ldsm4(al, sAlo + rowA * 72 + ks * 16 + ahalf);
#pragma unroll
        for (int j = 0; j < 3; ++j) {
            uint32_t bh[4], bl[4];
            int boff = (wn * 48 + j * 16 + rowB) * 72 + ks * 16 + bhalf;
            ldsm4(bh, sWhi + boff);
            ldsm4(bl, sWlo + boff);
            // bf16x3: hi*hi + lo*hi + hi*lo
            mma16816(acc[2 * j],     ah, bh[0], bh[1]);
            mma16816(acc[2 * j],     al, bh[0], bh[1]);
            mma16816(acc[2 * j],     ah, bl[0], bl[1]);
            mma16816(acc[2 * j + 1], ah, bh[2], bh[3]);
            mma16816(acc[2 * j + 1], al, bh[2], bh[3]);
            mma16816(acc[2 * j + 1], ah, bl[2], bl[3]);
        }
    }
}

// ---------------- fused GRU step (layer-pipelined, cp.async ring) ----------
// grid (32, LAYERS), 256 threads. CTA: 64 batch x 32 hidden units (96 gate rows).
__global__ __launch_bounds__(256) void gru_step_kernel(
    int gs, const float* __restrict__ bih, const float* __restrict__ bhh,
    float* __restrict__ out)
{
    const int l = blockIdx.y;
    const int t = gs - l;
    if (t < 0 || t >= S_LEN) return;

    const int u0   = blockIdx.x * 32;
    const int tid  = threadIdx.x;
    const int lane = tid & 31;
    const int wid  = tid >> 5;
    const int wm   = wid >> 1;   // 0..3  -> batch rows 16*wm
    const int wn   = wid & 1;    // 0..1  -> gate cols 48*wn

    extern __shared__ __align__(16) unsigned char smem_raw[];

    const int par = t & 1;

    const __nv_bfloat16* gA_hi[2];
    const __nv_bfloat16* gA_lo[2];
    const __nv_bfloat16* gW_hi[2];
    const __nv_bfloat16* gW_lo[2];
    if (l == 0) {
        gA_hi[0] = g_xhi + (size_t)t * BH;
        gA_lo[0] = g_xlo + (size_t)t * BH;
    } else {
        size_t o = ((size_t)(l - 1) * 2 + (par ^ 1)) * BH;  // h_{l-1}[t]
        gA_hi[0] = g_hhi + o;  gA_lo[0] = g_hlo + o;
    }
    {
        size_t o = ((size_t)l * 2 + par) * BH;               // h_l[t-1]
        gA_hi[1] = g_hhi + o;  gA_lo[1] = g_hlo + o;
    }
    {
        size_t o = (size_t)l * G3 * HID;
        gW_hi[0] = g_wih_hi + o;  gW_lo[0] = g_wih_lo + o;
        gW_hi[1] = g_whh_hi + o;  gW_lo[1] = g_whh_lo + o;
    }

    float acc[2][6][4];
#pragma unroll
    for (int p = 0; p < 2; ++p)
#pragma unroll
        for (int j = 0; j < 6; ++j)
#pragma unroll
            for (int q = 0; q < 4; ++q) acc[p][j][q] = 0.f;

    const int rowA  = wm * 16 + (lane & 15);
    const int ahalf = (lane >> 4) * 8;
    const int rowB  = (lane & 7) + ((lane & 16) ? 8 : 0);
    const int bhalf = (lane & 8) ? 8 : 0;

    // ---- prologue: prefetch first DEPTH-1 chunks ----
#pragma unroll
    for (int c = 0; c < DEPTH - 1; ++c) {
        __nv_bfloat16* buf = (__nv_bfloat16*)(smem_raw + (size_t)c * BUF_HALFS * 2);
        load_chunk(buf, gA_hi[0], gA_lo[0], gW_hi[0], gW_lo[0],
                   (c & 15) * 64, u0, tid);
        asm volatile("cp.async.commit_group;" ::: "memory");
    }

    // ---- main loop: 2 paths x 16 K-chunks, depth-4 ring ----
#pragma unroll
    for (int p = 0; p < 2; ++p) {
        for (int cc = 0; cc < 16; ++cc) {
            const int c = p * 16 + cc;
            asm volatile("cp.async.wait_group 2;" ::: "memory");
            __syncthreads();
            const int nc = c + DEPTH - 1;
            if (nc < NCHUNK) {
                const int np = nc >> 4;
                __nv_bfloat16* buf =
                    (__nv_bfloat16*)(smem_raw + (size_t)(nc % DEPTH) * BUF_HALFS * 2);
                load_chunk(buf, gA_hi[np], gA_lo[np], gW_hi[np], gW_lo[np],
                           (nc & 15) * 64, u0, tid);
            }
            asm volatile("cp.async.commit_group;" ::: "memory");  // always (drain-safe)
            const __nv_bfloat16* buf =
                (const __nv_bfloat16*)(smem_raw + (size_t)(c % DEPTH) * BUF_HALFS * 2);
            compute_chunk(buf, acc[p], rowA, ahalf, rowB, bhalf, wn);
        }
    }
    asm volatile("cp.async.wait_group 0;" ::: "memory");
    __syncthreads();

    // ---- epilogue: accums -> smem, then pointwise GRU update ----
    float* sGI = (float*)smem_raw;       // 64 x 96
    float* sGH = sGI + 64 * 96;          // 64 x 96
    {
        int g  = lane >> 2;
        int t4 = lane & 3;
#pragma unroll
        for (int j = 0; j < 6; ++j) {
            int col = wn * 48 + j * 8 + t4 * 2;
            int r0  = wm * 16 + g;
            sGI[r0 * 96 + col]           = acc[0][j][0];
            sGI[r0 * 96 + col + 1]       = acc[0][j][1];
            sGI[(r0 + 8) * 96 + col]     = acc[0][j][2];
            sGI[(r0 + 8) * 96 + col + 1] = acc[0][j][3];
            sGH[r0 * 96 + col]           = acc[1][j][0];
            sGH[r0 * 96 + col + 1]       = acc[1][j][1];
            sGH[(r0 + 8) * 96 + col]     = acc[1][j][2];
            sGH[(r0 + 8) * 96 + col + 1] = acc[1][j][3];
        }
    }
    __syncthreads();

    const int lG = l * G3;
    const float* bihp = bih + lG;
    const float* bhhp = bhh + lG;
    const float* hsrc = g_h + ((size_t)l * 2 + par) * BH;
    float*       hdst = g_h + ((size_t)l * 2 + (par ^ 1)) * BH;
    __nv_bfloat16* hhid = g_hhi + ((size_t)l * 2 + (par ^ 1)) * BH;
    __nv_bfloat16* hlod = g_hlo + ((size_t)l * 2 + (par ^ 1)) * BH;

#pragma unroll
    for (int it = 0; it < 8; ++it) {
        int idx = it * 256 + tid;
        int b = idx >> 5, u = idx & 31;
        int ug = u0 + u;
        float gi_r = sGI[b * 96 + u],       gh_r = sGH[b * 96 + u];
        float gi_z = sGI[b * 96 + 32 + u],  gh_z = sGH[b * 96 + 32 + u];
        float gi_n = sGI[b * 96 + 64 + u],  gh_n = sGH[b * 96 + 64 + u];
        float pr = gi_r + bihp[ug]           + gh_r + bhhp[ug];
        float pz = gi_z + bihp[HID + ug]     + gh_z + bhhp[HID + ug];
        float rg = 1.f / (1.f + __expf(-pr));
        float zg = 1.f / (1.f + __expf(-pz));
        float nn = tanhf(gi_n + bihp[2 * HID + ug] + rg * (gh_n + bhhp[2 * HID + ug]));
        float hold = hsrc[(size_t)b * HID + ug];
        float hn = (1.f - zg) * nn + zg * hold;
        hdst[(size_t)b * HID + ug] = hn;
        __nv_bfloat16 hi, lo;
        split2(hn, hi, lo);
        hhid[(size_t)b * HID + ug] = hi;
        hlod[(size_t)b * HID + ug] = lo;
        if (l == LAYERS - 1)
            out[(size_t)t * BH + (size_t)b * HID + ug] = hn;
    }
}

// ---------------- launch -----------------------------------------------------
extern "C" void kernel_launch(void* const* d_in, const int* in_sizes, int n_in,
                              void* d_out, int out_size)
{
    const float* x   = (const float*)d_in[0];
    const float* h0  = (const float*)d_in[1];
    const float* wih = (const float*)d_in[2];
    const float* whh = (const float*)d_in[3];
    const float* bih = (const float*)d_in[4];
    const float* bhh = (const float*)d_in[5];
    float* out = (float*)d_out;

    cudaFuncSetAttribute(gru_step_kernel,
                         cudaFuncAttributeMaxDynamicSharedMemorySize, SMEM_BYTES);

    {
        size_t n = (size_t)LAYERS * G3 * HID;
        split_weights_kernel<<<(unsigned)((n + 255) / 256), 256>>>(wih, whh);
    }
    {
        size_t n = (size_t)S_LEN * BH;
        split_x_kernel<<<(unsigned)((n + 255) / 256), 256>>>(x);
    }
    {
        size_t n = (size_t)LAYERS * BH;
        init_h_kernel<<<(unsigned)((n + 255) / 256), 256>>>(h0);
    }
    for (int gs = 0; gs < S_LEN + LAYERS - 1; ++gs)
        gru_step_kernel<<<dim3(32, LAYERS), 256, SMEM_BYTES>>>(gs, bih, bhh, out);
}